// round 1
// baseline (speedup 1.0000x reference)
#include <cuda_runtime.h>
#include <math.h>

#define B_TOTAL   262144
#define TILE      32
#define NTHREADS  256
#define IN_DIM    73
#define IN_PAD    76
#define HID       256
#define PI_F      3.14159265358979323846f
#define NORM_R    (500.0f/150000.0f)

// Padded, 16B-aligned copy of W_ih for float4 loads: [768][IN_PAD]
__device__ __align__(16) float g_Wih_pad[768 * IN_PAD];

struct SmemLayout {
    float sAT [IN_PAD][33];   // rnn_in transposed (k, row); k 73..75 zero
    float sHxT[HID][33];      // hx transposed; reused as F1 after GRU
    float sHT [HID][33];      // h_new, then h_ln in place
    float sF2T[128][33];      // f2
    float sXmT[6][32];        // x_minus
    float sMu[32];
    float sRstd[32];
};

__global__ void prep_weights_kernel(const float* __restrict__ W_ih) {
    int i = blockIdx.x * blockDim.x + threadIdx.x;
    if (i < 768 * IN_PAD) {
        int j = i / IN_PAD, k = i - j * IN_PAD;
        g_Wih_pad[i] = (k < IN_DIM) ? W_ih[j * IN_DIM + k] : 0.0f;
    }
}

__global__ __launch_bounds__(NTHREADS)
void knet_kernel(
    const float* __restrict__ meas, const float* __restrict__ mask,
    const float* __restrict__ dt,   const float* __restrict__ baselines,
    const float* __restrict__ x_prev, const float* __restrict__ hx,
    const float* __restrict__ W_hh,
    const float* __restrict__ b_ih, const float* __restrict__ b_hh,
    const float* __restrict__ ln_g, const float* __restrict__ ln_b,
    const float* __restrict__ W1, const float* __restrict__ b1,
    const float* __restrict__ W2, const float* __restrict__ b2,
    const float* __restrict__ W3, const float* __restrict__ b3,
    float* __restrict__ out_x, float* __restrict__ out_h)
{
    extern __shared__ float smem_raw[];
    SmemLayout& S = *reinterpret_cast<SmemLayout*>(smem_raw);

    const int tid  = threadIdx.x;
    const int lane = tid & 31;
    const int warp = tid >> 5;
    const int r0   = blockIdx.x * TILE;

    // ---- Load hx tile (contiguous 32*256 floats), store transposed ----
    {
        const float4* src = reinterpret_cast<const float4*>(hx + (size_t)r0 * HID);
        #pragma unroll
        for (int i = tid; i < TILE * HID / 4; i += NTHREADS) {
            float4 v = src[i];
            int e   = i * 4;
            int row = e >> 8;        // /256
            int k   = e & 255;
            S.sHxT[k + 0][row] = v.x;
            S.sHxT[k + 1][row] = v.y;
            S.sHxT[k + 2][row] = v.z;
            S.sHxT[k + 3][row] = v.w;
        }
    }

    // ---- Prep: x_minus, y_pred, innov, rnn_in (warp 0, lane = row) ----
    if (warp == 0) {
        const size_t r = (size_t)(r0 + lane);
        float dtv = dt[r];
        float xp[6];
        #pragma unroll
        for (int i = 0; i < 6; i++) xp[i] = x_prev[r * 6 + i];
        float bl[12];
        #pragma unroll
        for (int i = 0; i < 12; i++) bl[i] = baselines[r * 12 + i];

        float ds = dtv * NORM_R;
        float xm[6];
        xm[0] = fmaf(ds, xp[1], xp[0]); xm[1] = xp[1];
        xm[2] = fmaf(ds, xp[3], xp[2]); xm[3] = xp[3];
        xm[4] = fmaf(ds, xp[5], xp[4]); xm[5] = xp[5];
        #pragma unroll
        for (int i = 0; i < 6; i++) S.sXmT[i][lane] = xm[i];

        float yp[27];
        #pragma unroll
        for (int p = 0; p < 3; p++) {
            float x0 = xm[0], x2 = xm[2], x4 = xm[4];
            if (p == 1) { x0 -= bl[0]; x2 -= bl[2]; x4 -= bl[4]; }
            if (p == 2) { x0 -= bl[6]; x2 -= bl[8]; x4 -= bl[10]; }
            float rxy = sqrtf(x0 * x0 + x2 * x2 + 1e-9f);
            float az  = atan2f(x2, x0) * (1.0f / PI_F);
            float el  = atan2f(x4, rxy) * (1.0f / PI_F);
            float rr  = sqrtf(x0 * x0 + x2 * x2 + x4 * x4 + 1e-9f);
            yp[p * 9 + 0] = az; yp[p * 9 + 1] = el; yp[p * 9 + 2] = rr;
            yp[p * 9 + 3] = az; yp[p * 9 + 4] = el; yp[p * 9 + 5] = 0.0f;
            yp[p * 9 + 6] = az; yp[p * 9 + 7] = 0.0f; yp[p * 9 + 8] = 0.0f;
        }
        #pragma unroll
        for (int m = 0; m < 27; m++) {
            float mv = meas[r * 27 + m];
            float mk = mask[r * 27 + m];
            float in = mv - yp[m];
            int mm = m % 9;
            bool ang = (mm == 0) | (mm == 1) | (mm == 3) | (mm == 4) | (mm == 6);
            if (ang) in = in - 2.0f * rintf(in * 0.5f);   // wrap(in*pi)/pi
            in *= mk;
            S.sAT[m][lane]      = in;  // innov also consumed at the end
            S.sAT[27 + m][lane] = mk;
        }
        S.sAT[54][lane] = dtv;
        #pragma unroll
        for (int i = 0; i < 6; i++)  S.sAT[55 + i][lane] = xm[i];
        #pragma unroll
        for (int i = 0; i < 12; i++) S.sAT[61 + i][lane] = bl[i];
        S.sAT[73][lane] = 0.0f; S.sAT[74][lane] = 0.0f; S.sAT[75][lane] = 0.0f;
    }
    __syncthreads();

    // ---- GRU gates: warp w computes hidden units [w*32, w*32+32), lane = row ----
    for (int jj = 0; jj < 32; jj++) {
        const int j = warp * 32 + jj;
        float air = 0.f, aiz = 0.f, ain = 0.f;
        {
            const float4* wr = reinterpret_cast<const float4*>(g_Wih_pad + (j      ) * IN_PAD);
            const float4* wz = reinterpret_cast<const float4*>(g_Wih_pad + (j + 256) * IN_PAD);
            const float4* wn = reinterpret_cast<const float4*>(g_Wih_pad + (j + 512) * IN_PAD);
            #pragma unroll
            for (int i = 0; i < IN_PAD / 4; i++) {
                float a0 = S.sAT[4*i+0][lane], a1 = S.sAT[4*i+1][lane];
                float a2 = S.sAT[4*i+2][lane], a3 = S.sAT[4*i+3][lane];
                float4 r4 = wr[i], z4 = wz[i], n4 = wn[i];
                air = fmaf(a0, r4.x, air); air = fmaf(a1, r4.y, air);
                air = fmaf(a2, r4.z, air); air = fmaf(a3, r4.w, air);
                aiz = fmaf(a0, z4.x, aiz); aiz = fmaf(a1, z4.y, aiz);
                aiz = fmaf(a2, z4.z, aiz); aiz = fmaf(a3, z4.w, aiz);
                ain = fmaf(a0, n4.x, ain); ain = fmaf(a1, n4.y, ain);
                ain = fmaf(a2, n4.z, ain); ain = fmaf(a3, n4.w, ain);
            }
        }
        float ahr = 0.f, ahz = 0.f, ahn = 0.f;
        {
            const float4* vr = reinterpret_cast<const float4*>(W_hh + (size_t)(j      ) * HID);
            const float4* vz = reinterpret_cast<const float4*>(W_hh + (size_t)(j + 256) * HID);
            const float4* vn = reinterpret_cast<const float4*>(W_hh + (size_t)(j + 512) * HID);
            #pragma unroll 4
            for (int i = 0; i < HID / 4; i++) {
                float a0 = S.sHxT[4*i+0][lane], a1 = S.sHxT[4*i+1][lane];
                float a2 = S.sHxT[4*i+2][lane], a3 = S.sHxT[4*i+3][lane];
                float4 r4 = vr[i], z4 = vz[i], n4 = vn[i];
                ahr = fmaf(a0, r4.x, ahr); ahr = fmaf(a1, r4.y, ahr);
                ahr = fmaf(a2, r4.z, ahr); ahr = fmaf(a3, r4.w, ahr);
                ahz = fmaf(a0, z4.x, ahz); ahz = fmaf(a1, z4.y, ahz);
                ahz = fmaf(a2, z4.z, ahz); ahz = fmaf(a3, z4.w, ahz);
                ahn = fmaf(a0, n4.x, ahn); ahn = fmaf(a1, n4.y, ahn);
                ahn = fmaf(a2, n4.z, ahn); ahn = fmaf(a3, n4.w, ahn);
            }
        }
        float gr = air + ahr + b_ih[j]       + b_hh[j];
        float gz = aiz + ahz + b_ih[256 + j] + b_hh[256 + j];
        float rg = 1.0f / (1.0f + expf(-gr));
        float zg = 1.0f / (1.0f + expf(-gz));
        float nn = tanhf(ain + b_ih[512 + j] + rg * (ahn + b_hh[512 + j]));
        float hxv = S.sHxT[j][lane];
        S.sHT[j][lane] = (1.0f - zg) * nn + zg * hxv;
    }
    __syncthreads();

    // ---- Write h_new (coalesced), compute LN stats (reads only) ----
    {
        float4* dst = reinterpret_cast<float4*>(out_h + (size_t)r0 * HID);
        #pragma unroll
        for (int i = tid; i < TILE * HID / 4; i += NTHREADS) {
            int e   = i * 4;
            int row = e >> 8;
            int k   = e & 255;
            dst[i] = make_float4(S.sHT[k][row], S.sHT[k+1][row],
                                 S.sHT[k+2][row], S.sHT[k+3][row]);
        }
    }
    for (int rr = warp * 4; rr < warp * 4 + 4; rr++) {
        float s = 0.f, sq = 0.f;
        #pragma unroll
        for (int k = lane; k < HID; k += 32) {
            float v = S.sHT[k][rr];
            s += v; sq = fmaf(v, v, sq);
        }
        #pragma unroll
        for (int off = 16; off; off >>= 1) {
            s  += __shfl_xor_sync(0xffffffffu, s,  off);
            sq += __shfl_xor_sync(0xffffffffu, sq, off);
        }
        if (lane == 0) {
            float mu  = s * (1.0f / 256.0f);
            float var = sq * (1.0f / 256.0f) - mu * mu;
            S.sMu[rr]   = mu;
            S.sRstd[rr] = rsqrtf(var + 1e-5f);
        }
    }
    __syncthreads();

    // ---- Apply LayerNorm in place ----
    for (int idx = tid; idx < HID * TILE; idx += NTHREADS) {
        int j = idx >> 5, row = idx & 31;
        float v = S.sHT[j][row];
        S.sHT[j][row] = (v - S.sMu[row]) * S.sRstd[row] * ln_g[j] + ln_b[j];
    }
    __syncthreads();

    // ---- MLP layer 1: f1 = relu(h_ln @ W1^T + b1), reuse sHxT as F1 ----
    for (int jj = 0; jj < 32; jj++) {
        const int j = warp * 32 + jj;
        const float4* w4 = reinterpret_cast<const float4*>(W1 + (size_t)j * HID);
        float acc = 0.f;
        #pragma unroll 4
        for (int i = 0; i < HID / 4; i++) {
            float4 w = w4[i];
            acc = fmaf(S.sHT[4*i+0][lane], w.x, acc);
            acc = fmaf(S.sHT[4*i+1][lane], w.y, acc);
            acc = fmaf(S.sHT[4*i+2][lane], w.z, acc);
            acc = fmaf(S.sHT[4*i+3][lane], w.w, acc);
        }
        S.sHxT[j][lane] = fmaxf(acc + b1[j], 0.0f);
    }
    __syncthreads();

    // ---- MLP layer 2: f2 = relu(f1 @ W2^T + b2) ----
    for (int jj = 0; jj < 16; jj++) {
        const int j = warp * 16 + jj;
        const float4* w4 = reinterpret_cast<const float4*>(W2 + (size_t)j * HID);
        float acc = 0.f;
        #pragma unroll 4
        for (int i = 0; i < HID / 4; i++) {
            float4 w = w4[i];
            acc = fmaf(S.sHxT[4*i+0][lane], w.x, acc);
            acc = fmaf(S.sHxT[4*i+1][lane], w.y, acc);
            acc = fmaf(S.sHxT[4*i+2][lane], w.z, acc);
            acc = fmaf(S.sHxT[4*i+3][lane], w.w, acc);
        }
        S.sF2T[j][lane] = fmaxf(acc + b2[j], 0.0f);
    }
    __syncthreads();

    // ---- Gain head + correction: warp w = state s (<6), lane = row ----
    if (tid < 192) {
        const int row = lane;
        const int s   = warp;          // uniform per warp -> uniform W3 loads
        float corr = 0.f;
        for (int m = 0; m < 27; m++) {
            const float4* w4 = reinterpret_cast<const float4*>(W3 + (size_t)(s * 27 + m) * 128);
            float acc = 0.f;
            #pragma unroll 8
            for (int i = 0; i < 32; i++) {
                float4 w = w4[i];
                acc = fmaf(S.sF2T[4*i+0][row], w.x, acc);
                acc = fmaf(S.sF2T[4*i+1][row], w.y, acc);
                acc = fmaf(S.sF2T[4*i+2][row], w.z, acc);
                acc = fmaf(S.sF2T[4*i+3][row], w.w, acc);
            }
            acc += b3[s * 27 + m];
            acc = fminf(fmaxf(acc, -3.0f), 3.0f);
            corr = fmaf(acc, S.sAT[m][row], corr);   // innov lives in sAT[0..26]
        }
        float xn = S.sXmT[s][row] + corr;
        xn = fminf(fmaxf(xn, -5.0f), 5.0f);
        out_x[(size_t)(r0 + row) * 6 + s] = xn;
    }
}

extern "C" void kernel_launch(void* const* d_in, const int* in_sizes, int n_in,
                              void* d_out, int out_size)
{
    (void)in_sizes; (void)n_in; (void)out_size;
    const float* meas      = (const float*)d_in[0];
    const float* mask      = (const float*)d_in[1];
    const float* dtv       = (const float*)d_in[2];
    const float* baselines = (const float*)d_in[3];
    const float* x_prev    = (const float*)d_in[4];
    const float* hx        = (const float*)d_in[5];
    const float* W_ih      = (const float*)d_in[6];
    const float* W_hh      = (const float*)d_in[7];
    const float* b_ih      = (const float*)d_in[8];
    const float* b_hh      = (const float*)d_in[9];
    const float* ln_g      = (const float*)d_in[10];
    const float* ln_b      = (const float*)d_in[11];
    const float* W1        = (const float*)d_in[12];
    const float* b1        = (const float*)d_in[13];
    const float* W2        = (const float*)d_in[14];
    const float* b2        = (const float*)d_in[15];
    const float* W3        = (const float*)d_in[16];
    const float* b3        = (const float*)d_in[17];

    float* out   = (float*)d_out;
    float* out_x = out;                          // [B, 6]
    float* out_h = out + (size_t)B_TOTAL * 6;    // [B, 256]

    prep_weights_kernel<<<(768 * IN_PAD + 255) / 256, 256>>>(W_ih);

    const int smem_bytes = (int)sizeof(SmemLayout);
    cudaFuncSetAttribute(knet_kernel, cudaFuncAttributeMaxDynamicSharedMemorySize, smem_bytes);
    knet_kernel<<<B_TOTAL / TILE, NTHREADS, smem_bytes>>>(
        meas, mask, dtv, baselines, x_prev, hx, W_hh,
        b_ih, b_hh, ln_g, ln_b, W1, b1, W2, b2, W3, b3,
        out_x, out_h);
}

// round 2
// speedup vs baseline: 1.0004x; 1.0004x over previous
#include <cuda_runtime.h>
#include <math.h>

#define B_TOTAL   262144
#define TILE      32
#define NTHREADS  256
#define IN_DIM    73
#define IN_PAD    76
#define HID       256
#define PI_F      3.14159265358979323846f
#define NORM_R    (500.0f/150000.0f)

// Padded, 16B-aligned copy of W_ih for float4 loads: [768][IN_PAD]
__device__ __align__(16) float g_Wih_pad[768 * IN_PAD];

struct SmemLayout {
    float sAT [IN_PAD][33];   // rnn_in transposed (k, row); k 73..75 zero
    float sHxT[HID][33];      // hx transposed; reused as F1 after GRU
    float sHT [HID][33];      // h_new, then h_ln in place
    float sF2T[128][33];      // f2
    float sXmT[6][32];        // x_minus
    float sMu[32];
    float sRstd[32];
};

__global__ void prep_weights_kernel(const float* __restrict__ W_ih) {
    int i = blockIdx.x * blockDim.x + threadIdx.x;
    if (i < 768 * IN_PAD) {
        int j = i / IN_PAD, k = i - j * IN_PAD;
        g_Wih_pad[i] = (k < IN_DIM) ? W_ih[j * IN_DIM + k] : 0.0f;
    }
}

__global__ __launch_bounds__(NTHREADS)
void knet_kernel(
    const float* __restrict__ meas, const float* __restrict__ mask,
    const float* __restrict__ dt,   const float* __restrict__ baselines,
    const float* __restrict__ x_prev, const float* __restrict__ hx,
    const float* __restrict__ W_hh,
    const float* __restrict__ b_ih, const float* __restrict__ b_hh,
    const float* __restrict__ ln_g, const float* __restrict__ ln_b,
    const float* __restrict__ W1, const float* __restrict__ b1,
    const float* __restrict__ W2, const float* __restrict__ b2,
    const float* __restrict__ W3, const float* __restrict__ b3,
    float* __restrict__ out_x, float* __restrict__ out_h)
{
    extern __shared__ float smem_raw[];
    SmemLayout& S = *reinterpret_cast<SmemLayout*>(smem_raw);

    const int tid  = threadIdx.x;
    const int lane = tid & 31;
    const int warp = tid >> 5;
    const int r0   = blockIdx.x * TILE;

    // ---- Load hx tile (contiguous 32*256 floats), store transposed ----
    {
        const float4* src = reinterpret_cast<const float4*>(hx + (size_t)r0 * HID);
        #pragma unroll
        for (int i = tid; i < TILE * HID / 4; i += NTHREADS) {
            float4 v = src[i];
            int e   = i * 4;
            int row = e >> 8;        // /256
            int k   = e & 255;
            S.sHxT[k + 0][row] = v.x;
            S.sHxT[k + 1][row] = v.y;
            S.sHxT[k + 2][row] = v.z;
            S.sHxT[k + 3][row] = v.w;
        }
    }

    // ---- Prep: x_minus, y_pred, innov, rnn_in (warp 0, lane = row) ----
    if (warp == 0) {
        const size_t r = (size_t)(r0 + lane);
        float dtv = dt[r];
        float xp[6];
        #pragma unroll
        for (int i = 0; i < 6; i++) xp[i] = x_prev[r * 6 + i];
        float bl[12];
        #pragma unroll
        for (int i = 0; i < 12; i++) bl[i] = baselines[r * 12 + i];

        float ds = dtv * NORM_R;
        float xm[6];
        xm[0] = fmaf(ds, xp[1], xp[0]); xm[1] = xp[1];
        xm[2] = fmaf(ds, xp[3], xp[2]); xm[3] = xp[3];
        xm[4] = fmaf(ds, xp[5], xp[4]); xm[5] = xp[5];
        #pragma unroll
        for (int i = 0; i < 6; i++) S.sXmT[i][lane] = xm[i];

        float yp[27];
        #pragma unroll
        for (int p = 0; p < 3; p++) {
            float x0 = xm[0], x2 = xm[2], x4 = xm[4];
            if (p == 1) { x0 -= bl[0]; x2 -= bl[2]; x4 -= bl[4]; }
            if (p == 2) { x0 -= bl[6]; x2 -= bl[8]; x4 -= bl[10]; }
            float rxy = sqrtf(x0 * x0 + x2 * x2 + 1e-9f);
            float az  = atan2f(x2, x0) * (1.0f / PI_F);
            float el  = atan2f(x4, rxy) * (1.0f / PI_F);
            float rr  = sqrtf(x0 * x0 + x2 * x2 + x4 * x4 + 1e-9f);
            yp[p * 9 + 0] = az; yp[p * 9 + 1] = el; yp[p * 9 + 2] = rr;
            yp[p * 9 + 3] = az; yp[p * 9 + 4] = el; yp[p * 9 + 5] = 0.0f;
            yp[p * 9 + 6] = az; yp[p * 9 + 7] = 0.0f; yp[p * 9 + 8] = 0.0f;
        }
        #pragma unroll
        for (int m = 0; m < 27; m++) {
            float mv = meas[r * 27 + m];
            float mk = mask[r * 27 + m];
            float in = mv - yp[m];
            int mm = m % 9;
            bool ang = (mm == 0) | (mm == 1) | (mm == 3) | (mm == 4) | (mm == 6);
            if (ang) in = in - 2.0f * rintf(in * 0.5f);   // wrap(in*pi)/pi
            in *= mk;
            S.sAT[m][lane]      = in;  // innov also consumed at the end
            S.sAT[27 + m][lane] = mk;
        }
        S.sAT[54][lane] = dtv;
        #pragma unroll
        for (int i = 0; i < 6; i++)  S.sAT[55 + i][lane] = xm[i];
        #pragma unroll
        for (int i = 0; i < 12; i++) S.sAT[61 + i][lane] = bl[i];
        S.sAT[73][lane] = 0.0f; S.sAT[74][lane] = 0.0f; S.sAT[75][lane] = 0.0f;
    }
    __syncthreads();

    // ---- GRU gates: warp w computes hidden units [w*32, w*32+32), lane = row ----
    for (int jj = 0; jj < 32; jj++) {
        const int j = warp * 32 + jj;
        float air = 0.f, aiz = 0.f, ain = 0.f;
        {
            const float4* wr = reinterpret_cast<const float4*>(g_Wih_pad + (j      ) * IN_PAD);
            const float4* wz = reinterpret_cast<const float4*>(g_Wih_pad + (j + 256) * IN_PAD);
            const float4* wn = reinterpret_cast<const float4*>(g_Wih_pad + (j + 512) * IN_PAD);
            #pragma unroll
            for (int i = 0; i < IN_PAD / 4; i++) {
                float a0 = S.sAT[4*i+0][lane], a1 = S.sAT[4*i+1][lane];
                float a2 = S.sAT[4*i+2][lane], a3 = S.sAT[4*i+3][lane];
                float4 r4 = wr[i], z4 = wz[i], n4 = wn[i];
                air = fmaf(a0, r4.x, air); air = fmaf(a1, r4.y, air);
                air = fmaf(a2, r4.z, air); air = fmaf(a3, r4.w, air);
                aiz = fmaf(a0, z4.x, aiz); aiz = fmaf(a1, z4.y, aiz);
                aiz = fmaf(a2, z4.z, aiz); aiz = fmaf(a3, z4.w, aiz);
                ain = fmaf(a0, n4.x, ain); ain = fmaf(a1, n4.y, ain);
                ain = fmaf(a2, n4.z, ain); ain = fmaf(a3, n4.w, ain);
            }
        }
        float ahr = 0.f, ahz = 0.f, ahn = 0.f;
        {
            const float4* vr = reinterpret_cast<const float4*>(W_hh + (size_t)(j      ) * HID);
            const float4* vz = reinterpret_cast<const float4*>(W_hh + (size_t)(j + 256) * HID);
            const float4* vn = reinterpret_cast<const float4*>(W_hh + (size_t)(j + 512) * HID);
            #pragma unroll 4
            for (int i = 0; i < HID / 4; i++) {
                float a0 = S.sHxT[4*i+0][lane], a1 = S.sHxT[4*i+1][lane];
                float a2 = S.sHxT[4*i+2][lane], a3 = S.sHxT[4*i+3][lane];
                float4 r4 = vr[i], z4 = vz[i], n4 = vn[i];
                ahr = fmaf(a0, r4.x, ahr); ahr = fmaf(a1, r4.y, ahr);
                ahr = fmaf(a2, r4.z, ahr); ahr = fmaf(a3, r4.w, ahr);
                ahz = fmaf(a0, z4.x, ahz); ahz = fmaf(a1, z4.y, ahz);
                ahz = fmaf(a2, z4.z, ahz); ahz = fmaf(a3, z4.w, ahz);
                ahn = fmaf(a0, n4.x, ahn); ahn = fmaf(a1, n4.y, ahn);
                ahn = fmaf(a2, n4.z, ahn); ahn = fmaf(a3, n4.w, ahn);
            }
        }
        float gr = air + ahr + b_ih[j]       + b_hh[j];
        float gz = aiz + ahz + b_ih[256 + j] + b_hh[256 + j];
        float rg = 1.0f / (1.0f + expf(-gr));
        float zg = 1.0f / (1.0f + expf(-gz));
        float nn = tanhf(ain + b_ih[512 + j] + rg * (ahn + b_hh[512 + j]));
        float hxv = S.sHxT[j][lane];
        S.sHT[j][lane] = (1.0f - zg) * nn + zg * hxv;
    }
    __syncthreads();

    // ---- Write h_new (coalesced), compute LN stats (reads only) ----
    {
        float4* dst = reinterpret_cast<float4*>(out_h + (size_t)r0 * HID);
        #pragma unroll
        for (int i = tid; i < TILE * HID / 4; i += NTHREADS) {
            int e   = i * 4;
            int row = e >> 8;
            int k   = e & 255;
            dst[i] = make_float4(S.sHT[k][row], S.sHT[k+1][row],
                                 S.sHT[k+2][row], S.sHT[k+3][row]);
        }
    }
    for (int rr = warp * 4; rr < warp * 4 + 4; rr++) {
        float s = 0.f, sq = 0.f;
        #pragma unroll
        for (int k = lane; k < HID; k += 32) {
            float v = S.sHT[k][rr];
            s += v; sq = fmaf(v, v, sq);
        }
        #pragma unroll
        for (int off = 16; off; off >>= 1) {
            s  += __shfl_xor_sync(0xffffffffu, s,  off);
            sq += __shfl_xor_sync(0xffffffffu, sq, off);
        }
        if (lane == 0) {
            float mu  = s * (1.0f / 256.0f);
            float var = sq * (1.0f / 256.0f) - mu * mu;
            S.sMu[rr]   = mu;
            S.sRstd[rr] = rsqrtf(var + 1e-5f);
        }
    }
    __syncthreads();

    // ---- Apply LayerNorm in place ----
    for (int idx = tid; idx < HID * TILE; idx += NTHREADS) {
        int j = idx >> 5, row = idx & 31;
        float v = S.sHT[j][row];
        S.sHT[j][row] = (v - S.sMu[row]) * S.sRstd[row] * ln_g[j] + ln_b[j];
    }
    __syncthreads();

    // ---- MLP layer 1: f1 = relu(h_ln @ W1^T + b1), reuse sHxT as F1 ----
    for (int jj = 0; jj < 32; jj++) {
        const int j = warp * 32 + jj;
        const float4* w4 = reinterpret_cast<const float4*>(W1 + (size_t)j * HID);
        float acc = 0.f;
        #pragma unroll 4
        for (int i = 0; i < HID / 4; i++) {
            float4 w = w4[i];
            acc = fmaf(S.sHT[4*i+0][lane], w.x, acc);
            acc = fmaf(S.sHT[4*i+1][lane], w.y, acc);
            acc = fmaf(S.sHT[4*i+2][lane], w.z, acc);
            acc = fmaf(S.sHT[4*i+3][lane], w.w, acc);
        }
        S.sHxT[j][lane] = fmaxf(acc + b1[j], 0.0f);
    }
    __syncthreads();

    // ---- MLP layer 2: f2 = relu(f1 @ W2^T + b2) ----
    for (int jj = 0; jj < 16; jj++) {
        const int j = warp * 16 + jj;
        const float4* w4 = reinterpret_cast<const float4*>(W2 + (size_t)j * HID);
        float acc = 0.f;
        #pragma unroll 4
        for (int i = 0; i < HID / 4; i++) {
            float4 w = w4[i];
            acc = fmaf(S.sHxT[4*i+0][lane], w.x, acc);
            acc = fmaf(S.sHxT[4*i+1][lane], w.y, acc);
            acc = fmaf(S.sHxT[4*i+2][lane], w.z, acc);
            acc = fmaf(S.sHxT[4*i+3][lane], w.w, acc);
        }
        S.sF2T[j][lane] = fmaxf(acc + b2[j], 0.0f);
    }
    __syncthreads();

    // ---- Gain head + correction: warp w = state s (<6), lane = row ----
    if (tid < 192) {
        const int row = lane;
        const int s   = warp;          // uniform per warp -> uniform W3 loads
        float corr = 0.f;
        for (int m = 0; m < 27; m++) {
            const float4* w4 = reinterpret_cast<const float4*>(W3 + (size_t)(s * 27 + m) * 128);
            float acc = 0.f;
            #pragma unroll 8
            for (int i = 0; i < 32; i++) {
                float4 w = w4[i];
                acc = fmaf(S.sF2T[4*i+0][row], w.x, acc);
                acc = fmaf(S.sF2T[4*i+1][row], w.y, acc);
                acc = fmaf(S.sF2T[4*i+2][row], w.z, acc);
                acc = fmaf(S.sF2T[4*i+3][row], w.w, acc);
            }
            acc += b3[s * 27 + m];
            acc = fminf(fmaxf(acc, -3.0f), 3.0f);
            corr = fmaf(acc, S.sAT[m][row], corr);   // innov lives in sAT[0..26]
        }
        float xn = S.sXmT[s][row] + corr;
        xn = fminf(fmaxf(xn, -5.0f), 5.0f);
        out_x[(size_t)(r0 + row) * 6 + s] = xn;
    }
}

extern "C" void kernel_launch(void* const* d_in, const int* in_sizes, int n_in,
                              void* d_out, int out_size)
{
    (void)in_sizes; (void)n_in; (void)out_size;
    const float* meas      = (const float*)d_in[0];
    const float* mask      = (const float*)d_in[1];
    const float* dtv       = (const float*)d_in[2];
    const float* baselines = (const float*)d_in[3];
    const float* x_prev    = (const float*)d_in[4];
    const float* hx        = (const float*)d_in[5];
    const float* W_ih      = (const float*)d_in[6];
    const float* W_hh      = (const float*)d_in[7];
    const float* b_ih      = (const float*)d_in[8];
    const float* b_hh      = (const float*)d_in[9];
    const float* ln_g      = (const float*)d_in[10];
    const float* ln_b      = (const float*)d_in[11];
    const float* W1        = (const float*)d_in[12];
    const float* b1        = (const float*)d_in[13];
    const float* W2        = (const float*)d_in[14];
    const float* b2        = (const float*)d_in[15];
    const float* W3        = (const float*)d_in[16];
    const float* b3        = (const float*)d_in[17];

    float* out   = (float*)d_out;
    float* out_x = out;                          // [B, 6]
    float* out_h = out + (size_t)B_TOTAL * 6;    // [B, 256]

    prep_weights_kernel<<<(768 * IN_PAD + 255) / 256, 256>>>(W_ih);

    const int smem_bytes = (int)sizeof(SmemLayout);
    cudaFuncSetAttribute(knet_kernel, cudaFuncAttributeMaxDynamicSharedMemorySize, smem_bytes);
    knet_kernel<<<B_TOTAL / TILE, NTHREADS, smem_bytes>>>(
        meas, mask, dtv, baselines, x_prev, hx, W_hh,
        b_ih, b_hh, ln_g, ln_b, W1, b1, W2, b2, W3, b3,
        out_x, out_h);
}

// round 5
// speedup vs baseline: 5.2735x; 5.2713x over previous
#include <cuda_runtime.h>
#include <stdint.h>
#include <math.h>

#define B_TOTAL   262144
#define IN_DIM    73
#define KRNN      80          // rnn K padded to 80
#define HID       256
#define PI_F      3.14159265358979323846f
#define NORM_R    (500.0f/150000.0f)

// Packed weight region offsets (floats) inside g_Wg
#define WG_R      0           // [256][336]  r gate, [W_ih | pad | W_hh]
#define WG_Z      86016       // [256][336]  z gate
#define WG_GIN    172032      // [256][80]   gi_n (W_ih rows 512+j)
#define WG_GHN    192512      // [256][256]  gh_n (W_hh rows 512+j)
#define WG_TOTAL  258048

// ---------------- device scratch ----------------
__device__ __align__(16) float g_Arnn [(size_t)B_TOTAL * KRNN];   // pair-permuted, tf32
__device__ __align__(16) float g_innov[(size_t)B_TOTAL * 27];     // exact fp32
__device__ __align__(16) float g_xm   [(size_t)B_TOTAL * 6];      // exact fp32
__device__ __align__(16) float g_Wg   [WG_TOTAL];                 // packed gate weights
__device__ __align__(16) float g_bias [1024];                     // br, bz, bin, bhn
__device__ __align__(16) float g_W1p  [256 * 256];
__device__ __align__(16) float g_W2p  [128 * 256];
__device__ __align__(16) float g_W3p  [192 * 128];                // rows >=162 zero

// ---------------- helpers ----------------
__device__ __host__ __forceinline__ int ppf(int k) {              // pair-permute within k8
    return (k & ~7) + ((k & 3) << 1) + ((k >> 2) & 1);
}
__device__ __forceinline__ float tf32r(float x) {
    uint32_t r;
    asm("cvt.rna.tf32.f32 %0, %1;" : "=r"(r) : "f"(x));
    return __uint_as_float(r);
}
__device__ __forceinline__ void mma8(float* c, uint2 alo, uint2 ahi, uint2 b) {
    asm volatile(
        "mma.sync.aligned.m16n8k8.row.col.f32.tf32.tf32.f32 "
        "{%0,%1,%2,%3}, {%4,%5,%6,%7}, {%8,%9}, {%0,%1,%2,%3};"
        : "+f"(c[0]), "+f"(c[1]), "+f"(c[2]), "+f"(c[3])
        : "r"(alo.x), "r"(ahi.x), "r"(alo.y), "r"(ahi.y), "r"(b.x), "r"(b.y));
}
__device__ __forceinline__ float sigm(float x) { return 1.0f / (1.0f + expf(-x)); }

// ================= K0: pack weights =================
__global__ void pack_kernel(const float* __restrict__ W_ih, const float* __restrict__ W_hh,
                            const float* __restrict__ b_ih, const float* __restrict__ b_hh,
                            const float* __restrict__ W1, const float* __restrict__ W2,
                            const float* __restrict__ W3) {
    int i = blockIdx.x * blockDim.x + threadIdx.x;
    if (i < 2 * 256 * 336) {                       // r / z merged gates
        int g = i / (256 * 336);                   // 0=r, 1=z
        int j = (i / 336) % 256, k = i % 336;
        int row = g * 256 + j;                     // W row (r: j, z: 256+j)
        float v = 0.0f;
        if (k < IN_DIM)      v = W_ih[(size_t)row * IN_DIM + k];
        else if (k >= KRNN)  v = W_hh[(size_t)row * HID + (k - KRNN)];
        g_Wg[(g ? WG_Z : WG_R) + j * 336 + ppf(k)] = tf32r(v);
        return;
    }
    i -= 2 * 256 * 336;
    if (i < 256 * 80) {                            // gi_n
        int j = i / 80, k = i % 80;
        float v = (k < IN_DIM) ? W_ih[(size_t)(512 + j) * IN_DIM + k] : 0.0f;
        g_Wg[WG_GIN + j * 80 + ppf(k)] = tf32r(v);
        return;
    }
    i -= 256 * 80;
    if (i < 256 * 256) {                           // gh_n
        int j = i / 256, k = i % 256;
        g_Wg[WG_GHN + j * 256 + ppf(k)] = tf32r(W_hh[(size_t)(512 + j) * HID + k]);
        return;
    }
    i -= 256 * 256;
    if (i < 1024) {                                // biases (exact fp32)
        int j = i & 255, t = i >> 8;
        float v;
        if (t == 0)      v = b_ih[j]       + b_hh[j];
        else if (t == 1) v = b_ih[256 + j] + b_hh[256 + j];
        else if (t == 2) v = b_ih[512 + j];
        else             v = b_hh[512 + j];
        g_bias[i] = v;
        return;
    }
    i -= 1024;
    if (i < 256 * 256) {
        int n = i >> 8, k = i & 255;
        g_W1p[n * 256 + ppf(k)] = tf32r(W1[i]);
        return;
    }
    i -= 256 * 256;
    if (i < 128 * 256) {
        int n = i >> 8, k = i & 255;
        g_W2p[n * 256 + ppf(k)] = tf32r(W2[i]);
        return;
    }
    i -= 128 * 256;
    if (i < 192 * 128) {
        int n = i >> 7, k = i & 127;
        g_W3p[n * 128 + ppf(k)] = (n < 162) ? tf32r(W3[n * 128 + k]) : 0.0f;
    }
}
#define PACK_TOTAL (2*256*336 + 256*80 + 256*256 + 1024 + 256*256 + 128*256 + 192*128)

// ================= K1: per-row prep =================
__global__ __launch_bounds__(256)
void prep_kernel(const float* __restrict__ meas, const float* __restrict__ mask,
                 const float* __restrict__ dt,   const float* __restrict__ baselines,
                 const float* __restrict__ x_prev) {
    size_t r = (size_t)blockIdx.x * blockDim.x + threadIdx.x;
    if (r >= B_TOTAL) return;
    float dtv = dt[r];
    float xp[6], bl[12];
#pragma unroll
    for (int i = 0; i < 6; i++)  xp[i] = x_prev[r * 6 + i];
#pragma unroll
    for (int i = 0; i < 12; i++) bl[i] = baselines[r * 12 + i];
    float ds = dtv * NORM_R;
    float xm[6];
    xm[0] = fmaf(ds, xp[1], xp[0]); xm[1] = xp[1];
    xm[2] = fmaf(ds, xp[3], xp[2]); xm[3] = xp[3];
    xm[4] = fmaf(ds, xp[5], xp[4]); xm[5] = xp[5];
#pragma unroll
    for (int i = 0; i < 6; i++) g_xm[r * 6 + i] = xm[i];

    float yp[27];
#pragma unroll
    for (int p = 0; p < 3; p++) {
        float x0 = xm[0], x2 = xm[2], x4 = xm[4];
        if (p == 1) { x0 -= bl[0]; x2 -= bl[2]; x4 -= bl[4]; }
        if (p == 2) { x0 -= bl[6]; x2 -= bl[8]; x4 -= bl[10]; }
        float rxy = sqrtf(x0 * x0 + x2 * x2 + 1e-9f);
        float az  = atan2f(x2, x0) * (1.0f / PI_F);
        float el  = atan2f(x4, rxy) * (1.0f / PI_F);
        float rr  = sqrtf(x0 * x0 + x2 * x2 + x4 * x4 + 1e-9f);
        yp[p*9+0] = az; yp[p*9+1] = el; yp[p*9+2] = rr;
        yp[p*9+3] = az; yp[p*9+4] = el; yp[p*9+5] = 0.0f;
        yp[p*9+6] = az; yp[p*9+7] = 0.0f; yp[p*9+8] = 0.0f;
    }
    float* A = g_Arnn + r * KRNN;                  // pair-permuted writes
#pragma unroll
    for (int m = 0; m < 27; m++) {
        float mv = meas[r * 27 + m];
        float mk = mask[r * 27 + m];
        float in = mv - yp[m];
        int mm = m % 9;
        bool ang = (mm == 0) | (mm == 1) | (mm == 3) | (mm == 4) | (mm == 6);
        if (ang) in = in - 2.0f * rintf(in * 0.5f);
        in *= mk;
        g_innov[r * 27 + m] = in;
        A[ppf(m)]      = tf32r(in);
        A[ppf(27 + m)] = tf32r(mk);
    }
    A[ppf(54)] = tf32r(dtv);
#pragma unroll
    for (int i = 0; i < 6; i++)  A[ppf(55 + i)] = tf32r(xm[i]);
#pragma unroll
    for (int i = 0; i < 12; i++) A[ppf(61 + i)] = tf32r(bl[i]);
#pragma unroll
    for (int i = 73; i < KRNN; i++) A[ppf(i)] = 0.0f;
}

// ================= K2: GRU (M=128/CTA) =================
#define GS 360                                      // A-tile stride, 360 % 32 == 8
#define G_SMEM ((128 * GS + 1024) * 4)

__global__ __launch_bounds__(256, 1)
void gru_kernel(const float* __restrict__ hx, float* __restrict__ out_h) {
    extern __shared__ float sm[];
    float* sA    = sm;                              // [128][GS], logical [rnn 0..79 | hx 80..335]
    float* sBias = sm + 128 * GS;                   // [1024]
    const int tid = threadIdx.x, lane = tid & 31, wid = tid >> 5;
    const int wm = wid & 3, wn = wid >> 2;
    const int r0 = blockIdx.x * 128;

    // stage rnn part (already permuted + tf32 in gmem): straight float4 copy
    for (int t = tid; t < 128 * 20; t += 256) {
        int row = t / 20, s4 = (t % 20) * 4;
        float4 v = *(const float4*)(g_Arnn + (size_t)(r0 + row) * KRNN + s4);
        *(float4*)(sA + row * GS + s4) = v;
    }
    // stage hx (permute + tf32 round)
    for (int t = tid; t < 128 * 64; t += 256) {
        int row = t >> 6, kq = (t & 63) << 2;
        float4 v = *(const float4*)(hx + (size_t)(r0 + row) * HID + kq);
        int base = row * GS + 80 + (kq & ~7) + ((kq >> 2) & 1);
        sA[base]     = tf32r(v.x);
        sA[base + 2] = tf32r(v.y);
        sA[base + 4] = tf32r(v.z);
        sA[base + 6] = tf32r(v.w);
    }
    for (int t = tid; t < 1024; t += 256) sBias[t] = g_bias[t];
    __syncthreads();

    const int koff  = (lane & 3) << 1;
    const int rowA0 = wm * 32 + (lane >> 2);

    for (int pass = 0; pass < 4; pass++) {
        const int jb = pass * 64 + wn * 32;         // hidden-unit base for this warp
        float Cr[2][4][4], Cz[2][4][4], Cn[2][4][4], Ch[2][4][4];
#pragma unroll
        for (int mt = 0; mt < 2; mt++)
#pragma unroll
            for (int nt = 0; nt < 4; nt++)
#pragma unroll
                for (int e = 0; e < 4; e++) {
                    Cr[mt][nt][e] = 0.f; Cz[mt][nt][e] = 0.f;
                    Cn[mt][nt][e] = 0.f; Ch[mt][nt][e] = 0.f;
                }

        const float* BrP = g_Wg + WG_R   + (size_t)(jb + (lane >> 2)) * 336 + koff;
        const float* BzP = g_Wg + WG_Z   + (size_t)(jb + (lane >> 2)) * 336 + koff;
        const float* BiP = g_Wg + WG_GIN + (size_t)(jb + (lane >> 2)) * 80  + koff;
        const float* BhP = g_Wg + WG_GHN + (size_t)(jb + (lane >> 2)) * 256 + koff;

        // ---- r & z : K = 336 (42 ksteps) ----
        {
            uint2 br[4], bz[4];
#pragma unroll
            for (int nt = 0; nt < 4; nt++) {
                br[nt] = *(const uint2*)(BrP + nt * 2688);
                bz[nt] = *(const uint2*)(BzP + nt * 2688);
            }
            for (int ks = 0; ks < 42; ks++) {
                const int ksn = (ks < 41) ? ks + 1 : 41;
                uint2 brn[4], bzn[4];
#pragma unroll
                for (int nt = 0; nt < 4; nt++) {
                    brn[nt] = *(const uint2*)(BrP + nt * 2688 + ksn * 8);
                    bzn[nt] = *(const uint2*)(BzP + nt * 2688 + ksn * 8);
                }
                uint2 alo[2], ahi[2];
#pragma unroll
                for (int mt = 0; mt < 2; mt++) {
                    const float* ap = sA + (rowA0 + mt * 16) * GS + ks * 8 + koff;
                    alo[mt] = *(const uint2*)ap;
                    ahi[mt] = *(const uint2*)(ap + 8 * GS);
                }
#pragma unroll
                for (int nt = 0; nt < 4; nt++)
#pragma unroll
                    for (int mt = 0; mt < 2; mt++) {
                        mma8(Cr[mt][nt], alo[mt], ahi[mt], br[nt]);
                        mma8(Cz[mt][nt], alo[mt], ahi[mt], bz[nt]);
                    }
#pragma unroll
                for (int nt = 0; nt < 4; nt++) { br[nt] = brn[nt]; bz[nt] = bzn[nt]; }
            }
        }
        // ---- gi_n : K = 80 (10 ksteps) ----
        {
            uint2 bi[4];
#pragma unroll
            for (int nt = 0; nt < 4; nt++) bi[nt] = *(const uint2*)(BiP + nt * 640);
            for (int ks = 0; ks < 10; ks++) {
                const int ksn = (ks < 9) ? ks + 1 : 9;
                uint2 bin[4];
#pragma unroll
                for (int nt = 0; nt < 4; nt++)
                    bin[nt] = *(const uint2*)(BiP + nt * 640 + ksn * 8);
                uint2 alo[2], ahi[2];
#pragma unroll
                for (int mt = 0; mt < 2; mt++) {
                    const float* ap = sA + (rowA0 + mt * 16) * GS + ks * 8 + koff;
                    alo[mt] = *(const uint2*)ap;
                    ahi[mt] = *(const uint2*)(ap + 8 * GS);
                }
#pragma unroll
                for (int nt = 0; nt < 4; nt++)
#pragma unroll
                    for (int mt = 0; mt < 2; mt++)
                        mma8(Cn[mt][nt], alo[mt], ahi[mt], bi[nt]);
#pragma unroll
                for (int nt = 0; nt < 4; nt++) bi[nt] = bin[nt];
            }
        }
        // ---- gh_n : K = 256 (32 ksteps), A offset +80 ----
        {
            uint2 bh[4];
#pragma unroll
            for (int nt = 0; nt < 4; nt++) bh[nt] = *(const uint2*)(BhP + nt * 2048);
            for (int ks = 0; ks < 32; ks++) {
                const int ksn = (ks < 31) ? ks + 1 : 31;
                uint2 bhn[4];
#pragma unroll
                for (int nt = 0; nt < 4; nt++)
                    bhn[nt] = *(const uint2*)(BhP + nt * 2048 + ksn * 8);
                uint2 alo[2], ahi[2];
#pragma unroll
                for (int mt = 0; mt < 2; mt++) {
                    const float* ap = sA + (rowA0 + mt * 16) * GS + 80 + ks * 8 + koff;
                    alo[mt] = *(const uint2*)ap;
                    ahi[mt] = *(const uint2*)(ap + 8 * GS);
                }
#pragma unroll
                for (int nt = 0; nt < 4; nt++)
#pragma unroll
                    for (int mt = 0; mt < 2; mt++)
                        mma8(Ch[mt][nt], alo[mt], ahi[mt], bh[nt]);
#pragma unroll
                for (int nt = 0; nt < 4; nt++) bh[nt] = bhn[nt];
            }
        }
        // ---- epilogue: gates -> h, write out_h ----
#pragma unroll
        for (int mt = 0; mt < 2; mt++)
#pragma unroll
            for (int nt = 0; nt < 4; nt++)
#pragma unroll
                for (int half = 0; half < 2; half++) {
                    const int row = rowA0 + mt * 16 + half * 8;
                    const int jc  = jb + nt * 8 + ((lane & 3) << 1);
                    float h2[2];
#pragma unroll
                    for (int e = 0; e < 2; e++) {
                        const int j = jc + e;
                        const int idx = half * 2 + e;
                        float rg = sigm(Cr[mt][nt][idx] + sBias[j]);
                        float zg = sigm(Cz[mt][nt][idx] + sBias[256 + j]);
                        float nn = tanhf(Cn[mt][nt][idx] + sBias[512 + j]
                                         + rg * (Ch[mt][nt][idx] + sBias[768 + j]));
                        float hxv = sA[row * GS + 80 + (j & ~7) + ((j & 3) << 1) + ((j >> 2) & 1)];
                        h2[e] = (1.0f - zg) * nn + zg * hxv;
                    }
                    *(float2*)(out_h + (size_t)(r0 + row) * HID + jc) = make_float2(h2[0], h2[1]);
                }
    }
}

// ================= K3: LN + MLP + gain head (M=64/CTA) =================
#define S1 264
#define S3 136
#define SKV 200
#define OFF_A2  (64 * S1)
#define OFF_A3  (OFF_A2 + 64 * S1)
#define OFF_INN (OFF_A3 + 64 * S3)
#define M_SMEM  ((OFF_INN + 64 * 28) * 4)

__global__ __launch_bounds__(256, 1)
void mlp_kernel(const float* __restrict__ h_in,
                const float* __restrict__ ln_g, const float* __restrict__ ln_b,
                const float* __restrict__ b1, const float* __restrict__ b2,
                const float* __restrict__ b3, float* __restrict__ out_x) {
    extern __shared__ float sm[];
    float* sA1  = sm;                 // [64][S1] h_ln, later reused as kv [64][SKV]
    float* sA2  = sm + OFF_A2;        // [64][S1] f1
    float* sA3  = sm + OFF_A3;        // [64][S3] f2
    float* sInn = sm + OFF_INN;       // [64][28]
    const int tid = threadIdx.x, lane = tid & 31, wid = tid >> 5;
    const int wm = wid & 3, wn = wid >> 2;
    const int r0 = blockIdx.x * 64;

    // stage h (permute)
    for (int t = tid; t < 64 * 64; t += 256) {
        int row = t >> 6, kq = (t & 63) << 2;
        float4 v = *(const float4*)(h_in + (size_t)(r0 + row) * HID + kq);
        int base = row * S1 + (kq & ~7) + ((kq >> 2) & 1);
        sA1[base] = v.x; sA1[base + 2] = v.y; sA1[base + 4] = v.z; sA1[base + 6] = v.w;
    }
    for (int t = tid; t < 64 * 27; t += 256) {
        int row = t / 27, m = t % 27;
        sInn[row * 28 + m] = g_innov[(size_t)(r0 + row) * 27 + m];
    }
    __syncthreads();

    // LayerNorm (exact fp32 stats; tf32-round on store)
    {
        const int row = tid >> 2, q = tid & 3;
        float s = 0.f, sq = 0.f;
        for (int i = 0; i < 64; i++) {
            float v = sA1[row * S1 + q * 64 + i];
            s += v; sq = fmaf(v, v, sq);
        }
        s  += __shfl_xor_sync(0xffffffffu, s, 1);  sq += __shfl_xor_sync(0xffffffffu, sq, 1);
        s  += __shfl_xor_sync(0xffffffffu, s, 2);  sq += __shfl_xor_sync(0xffffffffu, sq, 2);
        float mu = s * (1.0f / 256.0f);
        float var = sq * (1.0f / 256.0f) - mu * mu;
        float rs = rsqrtf(var + 1e-5f);
        for (int i = 0; i < 64; i++) {
            int sp = q * 64 + i;
            int lc = (sp & ~7) + ((sp & 1) << 2) + ((sp >> 1) & 3);   // inverse perm
            float v = sA1[row * S1 + sp];
            sA1[row * S1 + sp] = tf32r((v - mu) * rs * __ldg(ln_g + lc) + __ldg(ln_b + lc));
        }
    }
    __syncthreads();

    const int koff  = (lane & 3) << 1;
    const int rowA0 = wm * 16 + (lane >> 2);

    // ---- MLP1: N=256 (4 passes), K=256, A=sA1 -> f1 in sA2 ----
    for (int p = 0; p < 4; p++) {
        const int nb = p * 64 + wn * 32;
        float C[4][4];
#pragma unroll
        for (int nt = 0; nt < 4; nt++)
#pragma unroll
            for (int e = 0; e < 4; e++) C[nt][e] = 0.f;
        const float* BP = g_W1p + (size_t)(nb + (lane >> 2)) * 256 + koff;
        uint2 b[4];
#pragma unroll
        for (int nt = 0; nt < 4; nt++) b[nt] = *(const uint2*)(BP + nt * 2048);
        for (int ks = 0; ks < 32; ks++) {
            const int ksn = (ks < 31) ? ks + 1 : 31;
            uint2 bn[4];
#pragma unroll
            for (int nt = 0; nt < 4; nt++) bn[nt] = *(const uint2*)(BP + nt * 2048 + ksn * 8);
            const float* ap = sA1 + rowA0 * S1 + ks * 8 + koff;
            uint2 alo = *(const uint2*)ap, ahi = *(const uint2*)(ap + 8 * S1);
#pragma unroll
            for (int nt = 0; nt < 4; nt++) mma8(C[nt], alo, ahi, b[nt]);
#pragma unroll
            for (int nt = 0; nt < 4; nt++) b[nt] = bn[nt];
        }
#pragma unroll
        for (int nt = 0; nt < 4; nt++)
#pragma unroll
            for (int half = 0; half < 2; half++) {
                const int row = rowA0 + half * 8;
                const int j0  = nb + nt * 8 + koff;
#pragma unroll
                for (int e = 0; e < 2; e++) {
                    int j = j0 + e;
                    float f = fmaxf(C[nt][half * 2 + e] + __ldg(b1 + j), 0.0f);
                    sA2[row * S1 + (j & ~7) + ((j & 3) << 1) + ((j >> 2) & 1)] = tf32r(f);
                }
            }
    }
    __syncthreads();

    // ---- MLP2: N=128 (2 passes), K=256, A=sA2 -> f2 in sA3 ----
    for (int p = 0; p < 2; p++) {
        const int nb = p * 64 + wn * 32;
        float C[4][4];
#pragma unroll
        for (int nt = 0; nt < 4; nt++)
#pragma unroll
            for (int e = 0; e < 4; e++) C[nt][e] = 0.f;
        const float* BP = g_W2p + (size_t)(nb + (lane >> 2)) * 256 + koff;
        uint2 b[4];
#pragma unroll
        for (int nt = 0; nt < 4; nt++) b[nt] = *(const uint2*)(BP + nt * 2048);
        for (int ks = 0; ks < 32; ks++) {
            const int ksn = (ks < 31) ? ks + 1 : 31;
            uint2 bn[4];
#pragma unroll
            for (int nt = 0; nt < 4; nt++) bn[nt] = *(const uint2*)(BP + nt * 2048 + ksn * 8);
            const float* ap = sA2 + rowA0 * S1 + ks * 8 + koff;
            uint2 alo = *(const uint2*)ap, ahi = *(const uint2*)(ap + 8 * S1);
#pragma unroll
            for (int nt = 0; nt < 4; nt++) mma8(C[nt], alo, ahi, b[nt]);
#pragma unroll
            for (int nt = 0; nt < 4; nt++) b[nt] = bn[nt];
        }
#pragma unroll
        for (int nt = 0; nt < 4; nt++)
#pragma unroll
            for (int half = 0; half < 2; half++) {
                const int row = rowA0 + half * 8;
                const int j0  = nb + nt * 8 + koff;
#pragma unroll
                for (int e = 0; e < 2; e++) {
                    int j = j0 + e;
                    float f = fmaxf(C[nt][half * 2 + e] + __ldg(b2 + j), 0.0f);
                    sA3[row * S3 + (j & ~7) + ((j & 3) << 1) + ((j >> 2) & 1)] = tf32r(f);
                }
            }
    }
    __syncthreads();

    // ---- MLP3: N=192 (3 passes), K=128, A=sA3 -> kv in sA1 (reused) ----
    for (int p = 0; p < 3; p++) {
        const int nb = p * 64 + wn * 32;
        float C[4][4];
#pragma unroll
        for (int nt = 0; nt < 4; nt++)
#pragma unroll
            for (int e = 0; e < 4; e++) C[nt][e] = 0.f;
        const float* BP = g_W3p + (size_t)(nb + (lane >> 2)) * 128 + koff;
        uint2 b[4];
#pragma unroll
        for (int nt = 0; nt < 4; nt++) b[nt] = *(const uint2*)(BP + nt * 1024);
        for (int ks = 0; ks < 16; ks++) {
            const int ksn = (ks < 15) ? ks + 1 : 15;
            uint2 bn[4];
#pragma unroll
            for (int nt = 0; nt < 4; nt++) bn[nt] = *(const uint2*)(BP + nt * 1024 + ksn * 8);
            const float* ap = sA3 + rowA0 * S3 + ks * 8 + koff;
            uint2 alo = *(const uint2*)ap, ahi = *(const uint2*)(ap + 8 * S3);
#pragma unroll
            for (int nt = 0; nt < 4; nt++) mma8(C[nt], alo, ahi, b[nt]);
#pragma unroll
            for (int nt = 0; nt < 4; nt++) b[nt] = bn[nt];
        }
#pragma unroll
        for (int nt = 0; nt < 4; nt++)
#pragma unroll
            for (int half = 0; half < 2; half++) {
                const int row = rowA0 + half * 8;
                const int j0  = nb + nt * 8 + koff;
#pragma unroll
                for (int e = 0; e < 2; e++) {
                    int j = j0 + e;
                    if (j < 162) {
                        float kv = C[nt][half * 2 + e] + __ldg(b3 + j);
                        sA1[row * SKV + j] = fminf(fmaxf(kv, -3.0f), 3.0f);
                    }
                }
            }
    }
    __syncthreads();

    // ---- correction + clamp ----
    for (int t = tid; t < 384; t += 256) {
        const int row = t & 63, s = t >> 6;
        float corr = 0.f;
#pragma unroll
        for (int m = 0; m < 27; m++)
            corr = fmaf(sA1[row * SKV + s * 27 + m], sInn[row * 28 + m], corr);
        float xmv = g_xm[(size_t)(r0 + row) * 6 + s];
        out_x[(size_t)(r0 + row) * 6 + s] = fminf(fmaxf(xmv + corr, -5.0f), 5.0f);
    }
}

// ================= launch =================
extern "C" void kernel_launch(void* const* d_in, const int* in_sizes, int n_in,
                              void* d_out, int out_size)
{
    (void)in_sizes; (void)n_in; (void)out_size;
    const float* meas      = (const float*)d_in[0];
    const float* mask      = (const float*)d_in[1];
    const float* dtv       = (const float*)d_in[2];
    const float* baselines = (const float*)d_in[3];
    const float* x_prev    = (const float*)d_in[4];
    const float* hx        = (const float*)d_in[5];
    const float* W_ih      = (const float*)d_in[6];
    const float* W_hh      = (const float*)d_in[7];
    const float* b_ih      = (const float*)d_in[8];
    const float* b_hh      = (const float*)d_in[9];
    const float* ln_g      = (const float*)d_in[10];
    const float* ln_b      = (const float*)d_in[11];
    const float* W1        = (const float*)d_in[12];
    const float* b1        = (const float*)d_in[13];
    const float* W2        = (const float*)d_in[14];
    const float* b2        = (const float*)d_in[15];
    const float* W3        = (const float*)d_in[16];
    const float* b3        = (const float*)d_in[17];

    float* out   = (float*)d_out;
    float* out_x = out;                            // [B, 6]
    float* out_h = out + (size_t)B_TOTAL * 6;      // [B, 256]

    pack_kernel<<<(PACK_TOTAL + 255) / 256, 256>>>(W_ih, W_hh, b_ih, b_hh, W1, W2, W3);
    prep_kernel<<<B_TOTAL / 256, 256>>>(meas, mask, dtv, baselines, x_prev);

    cudaFuncSetAttribute(gru_kernel, cudaFuncAttributeMaxDynamicSharedMemorySize, G_SMEM);
    gru_kernel<<<B_TOTAL / 128, 256, G_SMEM>>>(hx, out_h);

    cudaFuncSetAttribute(mlp_kernel, cudaFuncAttributeMaxDynamicSharedMemorySize, M_SMEM);
    mlp_kernel<<<B_TOTAL / 64, 256, M_SMEM>>>(out_h, ln_g, ln_b, b1, b2, b3, out_x);
}